// round 10
// baseline (speedup 1.0000x reference)
#include <cuda_runtime.h>
#include <cuda_fp16.h>
#include <cstdint>
#include <cstddef>

#define BB   8
#define NN   4096
#define KK   32
#define DD   64
#define CIN  67
#define MLPC 64
#define P1C  128
#define P2C  64
#define R2   0.04f
#define EPSF 1e-5f

// Scratch (device globals; no allocation allowed)
__device__ __half  Th_g[BB * NN * MLPC];   // fp16 s*(pts·Wd + xyz·Wx + b), 128B rows
__device__ float4  P4_g[BB * NN];          // (x, y, z, ||p||^2)
__device__ float   np_g[BB * NN * MLPC];   // max-pooled features, n-major rows
__device__ float4  sC4_g[MLPC];            // {s*Wx0, s*Wx1, s*Wx2, bt - s*rm}
__device__ float   Wt_g[CIN * MLPC];       // s-folded W, [c][o] layout
__device__ float   bs_g[MLPC];             // s*b

// ---- f32x2 packed helpers -------------------------------------------------
__device__ __forceinline__ void ffma2(unsigned long long& d,
                                      unsigned long long a,
                                      unsigned long long b) {
    asm("fma.rn.f32x2 %0, %1, %2, %0;" : "+l"(d) : "l"(a), "l"(b));
}
__device__ __forceinline__ void fadd2(unsigned long long& d, unsigned long long a) {
    asm("add.rn.f32x2 %0, %0, %1;" : "+l"(d) : "l"(a));
}
__device__ __forceinline__ unsigned long long pack2(float lo, float hi) {
    unsigned long long r;
    asm("mov.b64 %0, {%1, %2};" : "=l"(r) : "f"(lo), "f"(hi));
    return r;
}
__device__ __forceinline__ void unpack2(unsigned long long p, float& lo, float& hi) {
    asm("mov.b64 {%0, %1}, %2;" : "=f"(lo), "=f"(hi) : "l"(p));
}

// ---------------------------------------------------------------------------
// K0: one-time weight prep: Wt[c*64+o] = s[o]*W[o][c], sC4, bs
// ---------------------------------------------------------------------------
__global__ __launch_bounds__(256) void k_wprep(
    const float* __restrict__ W,  const float* __restrict__ bcv,
    const float* __restrict__ g,  const float* __restrict__ bt,
    const float* __restrict__ rm, const float* __restrict__ rv)
{
    int idx = blockIdx.x * 256 + threadIdx.x;
    if (idx < CIN * MLPC) {
        int o = idx & 63, c = idx >> 6;
        float s = g[o] / sqrtf(rv[o] + EPSF);
        Wt_g[idx] = s * W[o * CIN + c];
    }
    if (blockIdx.x == 0 && threadIdx.x < MLPC) {
        int o = threadIdx.x;
        float s = g[o] / sqrtf(rv[o] + EPSF);
        bs_g[o] = s * bcv[o];
        sC4_g[o] = make_float4(s * W[o * CIN + 64],
                               s * W[o * CIN + 65],
                               s * W[o * CIN + 66],
                               bt[o] - s * rm[o]);
    }
}

// ---------------------------------------------------------------------------
// K1: Th = X[32768x67] @ Wt[67x64], register-tiled GEMM, fp16 output.
// Block = 128 threads computes 32 points x 64 outs; thread = 2 pts x 8 outs.
// grid = 1024 blocks -> ~7 blocks/SM resident, ~7 warps/SMSP.
// ---------------------------------------------------------------------------
__global__ __launch_bounds__(128) void k_pre(
    const float* __restrict__ xyz, const float* __restrict__ pts)
{
    __shared__ float Wsh[CIN * MLPC];   // [c][o]  (16.75 KB)
    __shared__ float Xs[CIN * 32];      // [c][m]  (8.375 KB)

    int tid = threadIdx.x;

    // W: straight coalesced float4 copy (already transposed + s-folded)
    {
        const float4* src = (const float4*)Wt_g;
        float4* dst = (float4*)Wsh;
        for (int i = tid; i < CIN * MLPC / 4; i += 128) dst[i] = src[i];
    }

    int b  = blockIdx.x >> 7;              // 128 blocks per batch
    int m0 = (blockIdx.x & 127) << 5;      // 32 points per block

    // X: coalesced row copies; 67 rows x 8 float4
    for (int i = tid; i < CIN * 8; i += 128) {
        int c = i >> 3, j = (i & 7) << 2;
        const float* src = (c < DD) ? &pts[((b << 6) + c) * NN + m0 + j]
                                    : &xyz[(b * 3 + (c - DD)) * NN + m0 + j];
        *(float4*)&Xs[c * 32 + j] = *(const float4*)src;
    }
    __syncthreads();

    if (tid < 32) {
        float x = Xs[64 * 32 + tid], y = Xs[65 * 32 + tid], z = Xs[66 * 32 + tid];
        P4_g[b * NN + m0 + tid] = make_float4(x, y, z, fmaf(z, z, fmaf(y, y, x * x)));
    }

    int om = tid & 7;        // 8 out-groups of 8
    int pm = tid >> 3;       // 16 point-groups of 2

    unsigned long long acc0[4], acc1[4];
#pragma unroll
    for (int q = 0; q < 4; q++) { acc0[q] = 0ull; acc1[q] = 0ull; }

    const float* wp = &Wsh[om * 8];
    const float* xp = &Xs[pm * 2];

#pragma unroll 2
    for (int c = 0; c < CIN; c++) {
        float4 w0 = *(const float4*)(wp + c * MLPC);
        float4 w1 = *(const float4*)(wp + c * MLPC + 4);
        float2 xv = *(const float2*)(xp + c * 32);
        unsigned long long wv[4] = { pack2(w0.x, w0.y), pack2(w0.z, w0.w),
                                     pack2(w1.x, w1.y), pack2(w1.z, w1.w) };
        unsigned long long xx0 = pack2(xv.x, xv.x);
        unsigned long long xx1 = pack2(xv.y, xv.y);
#pragma unroll
        for (int q = 0; q < 4; q++) ffma2(acc0[q], wv[q], xx0);
#pragma unroll
        for (int q = 0; q < 4; q++) ffma2(acc1[q], wv[q], xx1);
    }

    float4 bsA = __ldg((const float4*)&bs_g[om * 8]);
    float4 bsB = __ldg((const float4*)&bs_g[om * 8 + 4]);
    float bsv[8] = { bsA.x, bsA.y, bsA.z, bsA.w, bsB.x, bsB.y, bsB.z, bsB.w };

    unsigned long long* accs[2] = { acc0, acc1 };
#pragma unroll
    for (int p = 0; p < 2; p++) {
        int gm = b * NN + m0 + pm * 2 + p;
        union { __half2 h2[4]; uint4 u4; } cvt;
#pragma unroll
        for (int q = 0; q < 4; q++) {
            float lo, hi;
            unpack2(accs[p][q], lo, hi);
            cvt.h2[q] = __floats2half2_rn(lo + bsv[2 * q], hi + bsv[2 * q + 1]);
        }
        *((uint4*)Th_g + (size_t)gm * 8 + om) = cvt.u4;
    }
}

// ---------------------------------------------------------------------------
// K2: ball query, 2 queries per warp (shared candidate loads) + fp16 gather-max
// block = 256 thr = 8 warps = 16 queries; grid = 2048
// ---------------------------------------------------------------------------
__global__ __launch_bounds__(256) void k_ball()
{
    __shared__ int gi_sh[16][KK];

    int tid  = threadIdx.x;
    int w    = tid >> 5;
    int lane = tid & 31;
    unsigned below = (1u << lane) - 1u;

    int b  = blockIdx.x >> 8;                   // 256 blocks per batch
    int nA = ((blockIdx.x & 255) << 4) + 2 * w; // 16 queries per block
    int nB = nA + 1;
    int bN = b * NN;

    float4 qA = P4_g[bN + nA];
    float4 qB = P4_g[bN + nB];

    int cntA = 0, cntB = 0;
#pragma unroll 1
    for (int base = 0; base < NN; base += 64) {
        float4 c0 = __ldg(&P4_g[bN + base + lane]);
        float4 c1 = __ldg(&P4_g[bN + base + 32 + lane]);

        float dA0 = qA.w + c0.w - 2.0f * fmaf(qA.z, c0.z, fmaf(qA.y, c0.y, qA.x * c0.x));
        float dA1 = qA.w + c1.w - 2.0f * fmaf(qA.z, c1.z, fmaf(qA.y, c1.y, qA.x * c1.x));
        float dB0 = qB.w + c0.w - 2.0f * fmaf(qB.z, c0.z, fmaf(qB.y, c0.y, qB.x * c0.x));
        float dB1 = qB.w + c1.w - 2.0f * fmaf(qB.z, c1.z, fmaf(qB.y, c1.y, qB.x * c1.x));

        unsigned mA0 = __ballot_sync(0xffffffffu, dA0 <= R2);
        unsigned mA1 = __ballot_sync(0xffffffffu, dA1 <= R2);
        unsigned mB0 = __ballot_sync(0xffffffffu, dB0 <= R2);
        unsigned mB1 = __ballot_sync(0xffffffffu, dB1 <= R2);

        if (dA0 <= R2) {
            int pos = cntA + __popc(mA0 & below);
            if (pos < KK) gi_sh[2 * w][pos] = base + lane;
        }
        int a0 = __popc(mA0);
        if (dA1 <= R2) {
            int pos = cntA + a0 + __popc(mA1 & below);
            if (pos < KK) gi_sh[2 * w][pos] = base + 32 + lane;
        }
        cntA += a0 + __popc(mA1);

        if (dB0 <= R2) {
            int pos = cntB + __popc(mB0 & below);
            if (pos < KK) gi_sh[2 * w + 1][pos] = base + lane;
        }
        int b0 = __popc(mB0);
        if (dB1 <= R2) {
            int pos = cntB + b0 + __popc(mB1 & below);
            if (pos < KK) gi_sh[2 * w + 1][pos] = base + 32 + lane;
        }
        cntB += b0 + __popc(mB1);

        if (cntA >= KK && cntB >= KK) break;
    }
    __syncwarp();

    int capA = (cntA < KK) ? cntA : KK;
    int capB = (cntB < KK) ? cntB : KK;
    int mygA = (lane < capA) ? gi_sh[2 * w][lane] : gi_sh[2 * w][0];
    int mygB = (lane < capB) ? gi_sh[2 * w + 1][lane] : gi_sh[2 * w + 1][0];

    __half2 mxA = __float2half2_rn(-65504.0f);
    __half2 mxB = mxA;
#pragma unroll
    for (int j = 0; j < KK; j++) {
        int gA = __shfl_sync(0xffffffffu, mygA, j);
        int gB = __shfl_sync(0xffffffffu, mygB, j);
        const __half2* base2 = (const __half2*)Th_g;
        mxA = __hmax2(mxA, __ldg(base2 + (((size_t)(bN + gA)) << 5) + lane));
        mxB = __hmax2(mxB, __ldg(base2 + (((size_t)(bN + gB)) << 5) + lane));
    }
    float2 mA = __half22float2(mxA);
    float2 mB = __half22float2(mxB);

    float4 a0c = sC4_g[2 * lane];
    float4 a1c = sC4_g[2 * lane + 1];

    float uA0 = a0c.w - fmaf(a0c.z, qA.z, fmaf(a0c.y, qA.y, a0c.x * qA.x));
    float uA1 = a1c.w - fmaf(a1c.z, qA.z, fmaf(a1c.y, qA.y, a1c.x * qA.x));
    float uB0 = a0c.w - fmaf(a0c.z, qB.z, fmaf(a0c.y, qB.y, a0c.x * qB.x));
    float uB1 = a1c.w - fmaf(a1c.z, qB.z, fmaf(a1c.y, qB.y, a1c.x * qB.x));

    *(float2*)&np_g[((size_t)(bN + nA)) * MLPC + 2 * lane] =
        make_float2(fmaxf(mA.x + uA0, 0.0f), fmaxf(mA.y + uA1, 0.0f));
    *(float2*)&np_g[((size_t)(bN + nB)) * MLPC + 2 * lane] =
        make_float2(fmaxf(mB.x + uB0, 0.0f), fmaxf(mB.y + uB1, 0.0f));
}

// ---------------------------------------------------------------------------
// K3: pointwise resnet 64->128->64 + residual ReLU, f32x2 packed FMA
// ---------------------------------------------------------------------------
__global__ __launch_bounds__(128) void k_resnet(
    const float* __restrict__ W1, const float* __restrict__ b1,
    const float* __restrict__ g1, const float* __restrict__ bt1,
    const float* __restrict__ rm1, const float* __restrict__ rv1,
    const float* __restrict__ W2, const float* __restrict__ b2,
    const float* __restrict__ g2, const float* __restrict__ bt2,
    const float* __restrict__ rm2, const float* __restrict__ rv2,
    const float* __restrict__ pts, float* __restrict__ out)
{
    extern __shared__ float sm[];
    float* W1sh  = sm;                  // [128][64] row-major
    float* W2Tsh = sm + P1C * P2C;      // [o][p] (W2 transposed)
    float* s1sh  = W2Tsh + P1C * P2C;
    float* t1sh  = s1sh + P1C;
    float* s2sh  = t1sh + P1C;
    float* t2sh  = s2sh + P2C;

    int tid = threadIdx.x;
    for (int i = tid; i < P1C * P2C; i += 128) {
        W1sh[i] = W1[i];
        W2Tsh[(i & (P1C - 1)) * P2C + (i >> 7)] = W2[i];
    }
    if (tid < P1C) {
        float s = g1[tid] / sqrtf(rv1[tid] + EPSF);
        s1sh[tid] = s;
        t1sh[tid] = fmaf(s, b1[tid] - rm1[tid], bt1[tid]);
    }
    if (tid < P2C) {
        float s = g2[tid] / sqrtf(rv2[tid] + EPSF);
        s2sh[tid] = s;
        t2sh[tid] = fmaf(s, b2[tid] - rm2[tid], bt2[tid]);
    }
    __syncthreads();

    int pt = blockIdx.x * 128 + tid;
    int b  = pt >> 12;
    int n  = pt & (NN - 1);

    unsigned long long v2[32];
    {
        const ulonglong2* vr = (const ulonglong2*)(np_g + (size_t)pt * MLPC);
#pragma unroll
        for (int i = 0; i < 16; i++) {
            ulonglong2 t = vr[i];
            v2[2 * i] = t.x;
            v2[2 * i + 1] = t.y;
        }
    }

    unsigned long long ap[32];
#pragma unroll
    for (int i = 0; i < 32; i++) ap[i] = 0ull;

#pragma unroll 2
    for (int o = 0; o < P1C; o++) {
        const ulonglong2* w1r = (const ulonglong2*)(W1sh + o * P2C);
        unsigned long long hp0 = 0ull, hp1 = 0ull, hp2 = 0ull, hp3 = 0ull;
#pragma unroll
        for (int i = 0; i < 8; i++) {
            ulonglong2 wa = w1r[2 * i];
            ulonglong2 wb = w1r[2 * i + 1];
            ffma2(hp0, wa.x, v2[4 * i + 0]);
            ffma2(hp1, wa.y, v2[4 * i + 1]);
            ffma2(hp2, wb.x, v2[4 * i + 2]);
            ffma2(hp3, wb.y, v2[4 * i + 3]);
        }
        fadd2(hp0, hp1);
        fadd2(hp2, hp3);
        fadd2(hp0, hp2);
        float hl, hh;
        unpack2(hp0, hl, hh);
        float h  = hl + hh;
        float x1 = fmaxf(fmaf(s1sh[o], h, t1sh[o]), 0.0f);
        unsigned long long X = pack2(x1, x1);

        const ulonglong2* w2r = (const ulonglong2*)(W2Tsh + o * P2C);
#pragma unroll
        for (int i = 0; i < 16; i++) {
            ulonglong2 wt = w2r[i];
            ffma2(ap[2 * i + 0], wt.x, X);
            ffma2(ap[2 * i + 1], wt.y, X);
        }
    }

#pragma unroll
    for (int i = 0; i < 32; i++) {
        float a0, a1;
        unpack2(ap[i], a0, a1);
        int p0 = 2 * i, p1 = 2 * i + 1;
        float v0 = fmaf(s2sh[p0], a0, t2sh[p0]) + pts[(b * P2C + p0) * NN + n];
        float v1 = fmaf(s2sh[p1], a1, t2sh[p1]) + pts[(b * P2C + p1) * NN + n];
        out[(b * P2C + p0) * NN + n] = fmaxf(v0, 0.0f);
        out[(b * P2C + p1) * NN + n] = fmaxf(v1, 0.0f);
    }
}

// ---------------------------------------------------------------------------
// Launch
// ---------------------------------------------------------------------------
extern "C" void kernel_launch(void* const* d_in, const int* in_sizes, int n_in,
                              void* d_out, int out_size)
{
    (void)n_in; (void)out_size;

    const float* xyz = (const float*)d_in[0];
    const float* pts = (const float*)d_in[1];
    const float* W   = (const float*)d_in[2];
    const float* bcv = (const float*)d_in[3];
    const float* g   = (const float*)d_in[4];
    const float* bt  = (const float*)d_in[5];
    const float* rm  = (const float*)d_in[6];
    const float* rv  = (const float*)d_in[7];
    const float* W1  = (const float*)d_in[8];
    const float* b1  = (const float*)d_in[9];
    const float* g1  = (const float*)d_in[10];
    const float* bt1 = (const float*)d_in[11];
    const float* rm1 = (const float*)d_in[12];
    const float* rv1 = (const float*)d_in[13];
    const float* W2  = (const float*)d_in[14];
    const float* b2  = (const float*)d_in[15];
    const float* g2  = (const float*)d_in[16];
    const float* bt2 = (const float*)d_in[17];
    const float* rm2 = (const float*)d_in[18];
    const float* rv2 = (const float*)d_in[19];

    float* out = (float*)d_out;

    static const size_t smem3 =
        (size_t)(P1C * P2C * 2 + P1C * 2 + P2C * 2) * sizeof(float);     // 67072 B
    cudaFuncSetAttribute(k_resnet, cudaFuncAttributeMaxDynamicSharedMemorySize,
                         (int)smem3);

    cudaMemcpyAsync(out, xyz, (size_t)in_sizes[0] * sizeof(float),
                    cudaMemcpyDeviceToDevice, 0);

    k_wprep<<<(CIN * MLPC + 255) / 256, 256>>>(W, bcv, g, bt, rm, rv);
    k_pre<<<(BB * NN) / 32, 128>>>(xyz, pts);
    k_ball<<<(BB * NN) / 16, 256>>>();
    k_resnet<<<(BB * NN) / 128, 128, smem3>>>(
        W1, b1, g1, bt1, rm1, rv1,
        W2, b2, g2, bt2, rm2, rv2,
        pts, out + in_sizes[0]);
}

// round 11
// speedup vs baseline: 1.1542x; 1.1542x over previous
#include <cuda_runtime.h>
#include <cuda_fp16.h>
#include <cstdint>
#include <cstddef>

#define BB   8
#define NN   4096
#define KK   32
#define DD   64
#define CIN  67
#define MLPC 64
#define P1C  128
#define P2C  64
#define R2   0.04f
#define EPSF 1e-5f

// Scratch (device globals; no allocation allowed)
__device__ __half  Th_g[BB * NN * MLPC];   // fp16 s*(pts·Wd + xyz·Wx + b), 128B rows
__device__ float4  P4_g[BB * NN];          // (x, y, z, ||p||^2)
__device__ float   np_g[BB * NN * MLPC];   // max-pooled features, n-major rows
__device__ float4  sC4_g[MLPC];            // {s*Wx0, s*Wx1, s*Wx2, bt - s*rm}
__device__ float   Wt_g[CIN * MLPC];       // s-folded W, [c][o] layout
__device__ float   bs_g[MLPC];             // s*b
__device__ float   W1t_g[P2C * P1C];       // s1-folded W1^T: [c][o] (64 x 128)
__device__ float   W2t_g[P1C * P2C];       // s2-folded W2^T: [o1][o2] (128 x 64)
__device__ float   t1_g[P1C];              // s1*(b1-rm1)+bt1
__device__ float   t2_g[P2C];              // s2*(b2-rm2)+bt2

// ---- f32x2 packed helpers -------------------------------------------------
__device__ __forceinline__ void ffma2(unsigned long long& d,
                                      unsigned long long a,
                                      unsigned long long b) {
    asm("fma.rn.f32x2 %0, %1, %2, %0;" : "+l"(d) : "l"(a), "l"(b));
}
__device__ __forceinline__ unsigned long long pack2(float lo, float hi) {
    unsigned long long r;
    asm("mov.b64 %0, {%1, %2};" : "=l"(r) : "f"(lo), "f"(hi));
    return r;
}
__device__ __forceinline__ void unpack2(unsigned long long p, float& lo, float& hi) {
    asm("mov.b64 {%0, %1}, %2;" : "=f"(lo), "=f"(hi) : "l"(p));
}

// ---------------------------------------------------------------------------
// K0: one-time weight prep for all layers (folded + transposed, coalesced)
// grid = 32 x 256 threads; gid covers max range 8192
// ---------------------------------------------------------------------------
__global__ __launch_bounds__(256) void k_wprep(
    const float* __restrict__ W,   const float* __restrict__ bcv,
    const float* __restrict__ g,   const float* __restrict__ bt,
    const float* __restrict__ rm,  const float* __restrict__ rv,
    const float* __restrict__ W1,  const float* __restrict__ b1,
    const float* __restrict__ g1,  const float* __restrict__ bt1,
    const float* __restrict__ rm1, const float* __restrict__ rv1,
    const float* __restrict__ W2,  const float* __restrict__ b2,
    const float* __restrict__ g2,  const float* __restrict__ bt2,
    const float* __restrict__ rm2, const float* __restrict__ rv2)
{
    int gid = blockIdx.x * 256 + threadIdx.x;

    if (gid < CIN * MLPC) {                    // layer-0 conv weights
        int o = gid & 63, c = gid >> 6;
        float s = g[o] / sqrtf(rv[o] + EPSF);
        Wt_g[gid] = s * W[o * CIN + c];
    }
    if (gid < P2C * P1C) {                     // W1T [c][o]
        int o = gid & 127, c = gid >> 7;
        float s1 = g1[o] / sqrtf(rv1[o] + EPSF);
        W1t_g[gid] = s1 * W1[o * P2C + c];
    }
    if (gid < P1C * P2C) {                     // W2T [o1][o2]
        int o2 = gid & 63, o1 = gid >> 6;
        float s2 = g2[o2] / sqrtf(rv2[o2] + EPSF);
        W2t_g[gid] = s2 * W2[o2 * P1C + o1];
    }
    if (gid < P1C) {
        float s1 = g1[gid] / sqrtf(rv1[gid] + EPSF);
        t1_g[gid] = fmaf(s1, b1[gid] - rm1[gid], bt1[gid]);
    }
    if (gid < P2C) {
        float s2 = g2[gid] / sqrtf(rv2[gid] + EPSF);
        t2_g[gid] = fmaf(s2, b2[gid] - rm2[gid], bt2[gid]);
    }
    if (gid < MLPC) {
        int o = gid;
        float s = g[o] / sqrtf(rv[o] + EPSF);
        bs_g[o] = s * bcv[o];
        sC4_g[o] = make_float4(s * W[o * CIN + 64],
                               s * W[o * CIN + 65],
                               s * W[o * CIN + 66],
                               bt[o] - s * rm[o]);
    }
}

// ---------------------------------------------------------------------------
// K1: Th = X[32768x67] @ Wt[67x64], register-tiled GEMM, fp16 output.
// Block = 128 threads computes 32 points x 64 outs; thread = 2 pts x 8 outs.
// ---------------------------------------------------------------------------
__global__ __launch_bounds__(128) void k_pre(
    const float* __restrict__ xyz, const float* __restrict__ pts)
{
    __shared__ float Wsh[CIN * MLPC];   // [c][o]  (16.75 KB)
    __shared__ float Xs[CIN * 32];      // [c][m]  (8.375 KB)

    int tid = threadIdx.x;

    {
        const float4* src = (const float4*)Wt_g;
        float4* dst = (float4*)Wsh;
        for (int i = tid; i < CIN * MLPC / 4; i += 128) dst[i] = src[i];
    }

    int b  = blockIdx.x >> 7;
    int m0 = (blockIdx.x & 127) << 5;

    for (int i = tid; i < CIN * 8; i += 128) {
        int c = i >> 3, j = (i & 7) << 2;
        const float* src = (c < DD) ? &pts[((b << 6) + c) * NN + m0 + j]
                                    : &xyz[(b * 3 + (c - DD)) * NN + m0 + j];
        *(float4*)&Xs[c * 32 + j] = *(const float4*)src;
    }
    __syncthreads();

    if (tid < 32) {
        float x = Xs[64 * 32 + tid], y = Xs[65 * 32 + tid], z = Xs[66 * 32 + tid];
        P4_g[b * NN + m0 + tid] = make_float4(x, y, z, fmaf(z, z, fmaf(y, y, x * x)));
    }

    int om = tid & 7;
    int pm = tid >> 3;

    unsigned long long acc0[4], acc1[4];
#pragma unroll
    for (int q = 0; q < 4; q++) { acc0[q] = 0ull; acc1[q] = 0ull; }

    const float* wp = &Wsh[om * 8];
    const float* xp = &Xs[pm * 2];

#pragma unroll 2
    for (int c = 0; c < CIN; c++) {
        float4 w0 = *(const float4*)(wp + c * MLPC);
        float4 w1 = *(const float4*)(wp + c * MLPC + 4);
        float2 xv = *(const float2*)(xp + c * 32);
        unsigned long long wv[4] = { pack2(w0.x, w0.y), pack2(w0.z, w0.w),
                                     pack2(w1.x, w1.y), pack2(w1.z, w1.w) };
        unsigned long long xx0 = pack2(xv.x, xv.x);
        unsigned long long xx1 = pack2(xv.y, xv.y);
#pragma unroll
        for (int q = 0; q < 4; q++) ffma2(acc0[q], wv[q], xx0);
#pragma unroll
        for (int q = 0; q < 4; q++) ffma2(acc1[q], wv[q], xx1);
    }

    float4 bsA = __ldg((const float4*)&bs_g[om * 8]);
    float4 bsB = __ldg((const float4*)&bs_g[om * 8 + 4]);
    float bsv[8] = { bsA.x, bsA.y, bsA.z, bsA.w, bsB.x, bsB.y, bsB.z, bsB.w };

    unsigned long long* accs[2] = { acc0, acc1 };
#pragma unroll
    for (int p = 0; p < 2; p++) {
        int gm = b * NN + m0 + pm * 2 + p;
        union { __half2 h2[4]; uint4 u4; } cvt;
#pragma unroll
        for (int q = 0; q < 4; q++) {
            float lo, hi;
            unpack2(accs[p][q], lo, hi);
            cvt.h2[q] = __floats2half2_rn(lo + bsv[2 * q], hi + bsv[2 * q + 1]);
        }
        *((uint4*)Th_g + (size_t)gm * 8 + om) = cvt.u4;
    }
}

// ---------------------------------------------------------------------------
// K2: warp-autonomous ball query (R8 version) + fp16 gather-max
// ---------------------------------------------------------------------------
__global__ __launch_bounds__(256) void k_ball()
{
    __shared__ int gi_sh[8][KK];

    int tid  = threadIdx.x;
    int w    = tid >> 5;
    int lane = tid & 31;
    unsigned below = (1u << lane) - 1u;

    int b  = blockIdx.x >> 9;
    int n  = ((blockIdx.x & 511) << 3) + w;
    int bN = b * NN;

    float4 q = P4_g[bN + n];

    int cnt = 0;
#pragma unroll 1
    for (int base = 0; base < NN; base += 64) {
        float4 c0 = __ldg(&P4_g[bN + base + lane]);
        float4 c1 = __ldg(&P4_g[bN + base + 32 + lane]);

        float d0 = q.w + c0.w - 2.0f * fmaf(q.z, c0.z, fmaf(q.y, c0.y, q.x * c0.x));
        float d1 = q.w + c1.w - 2.0f * fmaf(q.z, c1.z, fmaf(q.y, c1.y, q.x * c1.x));

        unsigned m0 = __ballot_sync(0xffffffffu, d0 <= R2);
        unsigned m1 = __ballot_sync(0xffffffffu, d1 <= R2);

        if (d0 <= R2) {
            int pos = cnt + __popc(m0 & below);
            if (pos < KK) gi_sh[w][pos] = base + lane;
        }
        int n0 = __popc(m0);
        if (d1 <= R2) {
            int pos = cnt + n0 + __popc(m1 & below);
            if (pos < KK) gi_sh[w][pos] = base + 32 + lane;
        }
        cnt += n0 + __popc(m1);
        if (cnt >= KK) break;
    }
    __syncwarp();

    int cap   = (cnt < KK) ? cnt : KK;
    int gidx0 = gi_sh[w][0];

    __half2 mx = __float2half2_rn(-65504.0f);
#pragma unroll
    for (int j = 0; j < KK; j++) {
        int gj = (j < cap) ? gi_sh[w][j] : gidx0;
        const __half2* tr = ((const __half2*)Th_g) + (((size_t)(bN + gj)) << 5) + lane;
        mx = __hmax2(mx, __ldg(tr));
    }
    float2 m = __half22float2(mx);

    float4 a0 = sC4_g[2 * lane];
    float4 a1 = sC4_g[2 * lane + 1];
    float u0 = a0.w - fmaf(a0.z, q.z, fmaf(a0.y, q.y, a0.x * q.x));
    float u1 = a1.w - fmaf(a1.z, q.z, fmaf(a1.y, q.y, a1.x * q.x));

    float2 outv = make_float2(fmaxf(m.x + u0, 0.0f), fmaxf(m.y + u1, 0.0f));
    *(float2*)&np_g[((size_t)(bN + n)) * MLPC + 2 * lane] = outv;
}

// ---------------------------------------------------------------------------
// K3: resnet 64->128->64 + residual ReLU as two-phase tiled GEMM.
// Block = 128 thr, 64 points. smem: A = W1T(32KB) -> X1(32KB),
//                                    B = Vt(17KB) -> W2T(32KB). Total 64KB.
// Phase1 thread tile: 4 pts x 16 o.  Phase2: 4 pts x 8 o2.
// ---------------------------------------------------------------------------
__global__ __launch_bounds__(128) void k_resnet(
    const float* __restrict__ pts, float* __restrict__ out)
{
    extern __shared__ float sm[];
    float* A  = sm;          // 8192 floats
    float* Bq = sm + 8192;   // 8192 floats

    int tid = threadIdx.x;
    int m0  = blockIdx.x << 6;          // 64 points per block
    int b   = m0 >> 12;
    int n0  = m0 & (NN - 1);

    // Load W1T (coalesced, pre-folded/transposed)
    for (int i = tid; i < 2048; i += 128)
        ((float4*)A)[i] = ((const float4*)W1t_g)[i];

    // Load V transposed: Vt[c][pt], stride 68 (pad kills store conflicts)
    for (int i = tid; i < 1024; i += 128) {
        int pt = i >> 4, c4 = (i & 15) << 2;
        float4 v = *(const float4*)&np_g[(size_t)(m0 + pt) * MLPC + c4];
        Bq[(c4 + 0) * 68 + pt] = v.x;
        Bq[(c4 + 1) * 68 + pt] = v.y;
        Bq[(c4 + 2) * 68 + pt] = v.z;
        Bq[(c4 + 3) * 68 + pt] = v.w;
    }
    __syncthreads();

    int om = tid >> 4;      // 0..7 -> 16 o each
    int pm = tid & 15;      // 0..15 -> 4 pts each

    // ---- Phase 1: H = V @ W1T ----
    unsigned long long acc1[4][8];
#pragma unroll
    for (int p = 0; p < 4; p++)
#pragma unroll
        for (int q = 0; q < 8; q++) acc1[p][q] = 0ull;

    {
        const float* wrow = A + om * 16;
        const float* vrow = Bq + 4 * pm;
#pragma unroll 2
        for (int k = 0; k < P2C; k++) {
            float4 w0 = *(const float4*)(wrow + k * P1C);
            float4 w1 = *(const float4*)(wrow + k * P1C + 4);
            float4 w2 = *(const float4*)(wrow + k * P1C + 8);
            float4 w3 = *(const float4*)(wrow + k * P1C + 12);
            float4 vv = *(const float4*)(vrow + k * 68);
            unsigned long long wv[8] = {
                pack2(w0.x, w0.y), pack2(w0.z, w0.w),
                pack2(w1.x, w1.y), pack2(w1.z, w1.w),
                pack2(w2.x, w2.y), pack2(w2.z, w2.w),
                pack2(w3.x, w3.y), pack2(w3.z, w3.w) };
            float vs[4] = { vv.x, vv.y, vv.z, vv.w };
#pragma unroll
            for (int p = 0; p < 4; p++) {
                unsigned long long xx = pack2(vs[p], vs[p]);
#pragma unroll
                for (int q = 0; q < 8; q++) ffma2(acc1[p][q], wv[q], xx);
            }
        }
    }
    __syncthreads();   // everyone done reading W1T / Vt

    // X1 epilogue into A: X1[o*64 + pt] = relu(h + t1)
#pragma unroll
    for (int k = 0; k < 16; k++) {
        int o = om * 16 + k;
        float t1v = __ldg(&t1_g[o]);
        float4 xv;
        float* xp = (float*)&xv;
#pragma unroll
        for (int p = 0; p < 4; p++) {
            float lo, hi;
            unpack2(acc1[p][k >> 1], lo, hi);
            float val = (k & 1) ? hi : lo;
            xp[p] = fmaxf(val + t1v, 0.0f);
        }
        *(float4*)&A[o * P2C + 4 * pm] = xv;
    }

    // Load W2T into B
    for (int i = tid; i < 2048; i += 128)
        ((float4*)Bq)[i] = ((const float4*)W2t_g)[i];
    __syncthreads();

    // ---- Phase 2: out = X1 @ W2T + t2 + pts, relu ----
    unsigned long long acc2[4][4];
#pragma unroll
    for (int p = 0; p < 4; p++)
#pragma unroll
        for (int q = 0; q < 4; q++) acc2[p][q] = 0ull;

    {
        const float* wrow = Bq + om * 8;
        const float* xrow = A + 4 * pm;
#pragma unroll 2
        for (int k = 0; k < P1C; k++) {
            float4 w0 = *(const float4*)(wrow + k * P2C);
            float4 w1 = *(const float4*)(wrow + k * P2C + 4);
            float4 xv = *(const float4*)(xrow + k * P2C);
            unsigned long long wv[4] = {
                pack2(w0.x, w0.y), pack2(w0.z, w0.w),
                pack2(w1.x, w1.y), pack2(w1.z, w1.w) };
            float xs[4] = { xv.x, xv.y, xv.z, xv.w };
#pragma unroll
            for (int p = 0; p < 4; p++) {
                unsigned long long xx = pack2(xs[p], xs[p]);
#pragma unroll
                for (int q = 0; q < 4; q++) ffma2(acc2[p][q], wv[q], xx);
            }
        }
    }

#pragma unroll
    for (int k = 0; k < 8; k++) {
        int o2 = om * 8 + k;
        float t2v = __ldg(&t2_g[o2]);
        size_t goff = ((size_t)(b * P2C + o2)) * NN + n0 + 4 * pm;
        float4 pv = *(const float4*)&pts[goff];
        float4 ov;
        float* op = (float*)&ov;
        float* pp = (float*)&pv;
#pragma unroll
        for (int p = 0; p < 4; p++) {
            float lo, hi;
            unpack2(acc2[p][k >> 1], lo, hi);
            float val = (k & 1) ? hi : lo;
            op[p] = fmaxf(val + t2v + pp[p], 0.0f);
        }
        *(float4*)&out[goff] = ov;
    }
}

// ---------------------------------------------------------------------------
// Launch
// ---------------------------------------------------------------------------
extern "C" void kernel_launch(void* const* d_in, const int* in_sizes, int n_in,
                              void* d_out, int out_size)
{
    (void)n_in; (void)out_size;

    const float* xyz = (const float*)d_in[0];
    const float* pts = (const float*)d_in[1];
    const float* W   = (const float*)d_in[2];
    const float* bcv = (const float*)d_in[3];
    const float* g   = (const float*)d_in[4];
    const float* bt  = (const float*)d_in[5];
    const float* rm  = (const float*)d_in[6];
    const float* rv  = (const float*)d_in[7];
    const float* W1  = (const float*)d_in[8];
    const float* b1  = (const float*)d_in[9];
    const float* g1  = (const float*)d_in[10];
    const float* bt1 = (const float*)d_in[11];
    const float* rm1 = (const float*)d_in[12];
    const float* rv1 = (const float*)d_in[13];
    const float* W2  = (const float*)d_in[14];
    const float* b2  = (const float*)d_in[15];
    const float* g2  = (const float*)d_in[16];
    const float* bt2 = (const float*)d_in[17];
    const float* rm2 = (const float*)d_in[18];
    const float* rv2 = (const float*)d_in[19];

    float* out = (float*)d_out;

    static const size_t smem3 = 16384 * sizeof(float);   // 65536 B
    cudaFuncSetAttribute(k_resnet, cudaFuncAttributeMaxDynamicSharedMemorySize,
                         (int)smem3);

    cudaMemcpyAsync(out, xyz, (size_t)in_sizes[0] * sizeof(float),
                    cudaMemcpyDeviceToDevice, 0);

    k_wprep<<<32, 256>>>(W, bcv, g, bt, rm, rv,
                         W1, b1, g1, bt1, rm1, rv1,
                         W2, b2, g2, bt2, rm2, rv2);
    k_pre<<<(BB * NN) / 32, 128>>>(xyz, pts);
    k_ball<<<(BB * NN) / 8, 256>>>();
    k_resnet<<<(BB * NN) / 64, 128, smem3>>>(pts, out + in_sizes[0]);
}

// round 12
// speedup vs baseline: 1.1734x; 1.0167x over previous
#include <cuda_runtime.h>
#include <cuda_fp16.h>
#include <cstdint>
#include <cstddef>

#define BB   8
#define NN   4096
#define KK   32
#define DD   64
#define CIN  67
#define MLPC 64
#define P1C  128
#define P2C  64
#define R2   0.04f
#define EPSF 1e-5f

// Scratch (device globals; no allocation allowed)
__device__ __half  Th_g[BB * NN * MLPC];   // fp16 s*(pts·Wd + xyz·Wx + b), 128B rows
__device__ float4  P4_g[BB * NN];          // (x, y, z, ||p||^2)
__device__ float   np_g[BB * NN * MLPC];   // max-pooled features, n-major rows
__device__ float4  sC4_g[MLPC];            // {s*Wx0, s*Wx1, s*Wx2, bt - s*rm}
__device__ float   Wt_g[CIN * MLPC];       // s-folded W, [c][o] layout
__device__ float   bs_g[MLPC];             // s*b
__device__ float   W1t_g[P2C * P1C];       // s1-folded W1^T: [c][o] (64 x 128)
__device__ float   W2t_g[P1C * P2C];       // s2-folded W2^T: [o1][o2] (128 x 64)
__device__ float   t1_g[P1C];              // s1*(b1-rm1)+bt1
__device__ float   t2_g[P2C];              // s2*(b2-rm2)+bt2

// ---- f32x2 packed helpers -------------------------------------------------
__device__ __forceinline__ void ffma2(unsigned long long& d,
                                      unsigned long long a,
                                      unsigned long long b) {
    asm("fma.rn.f32x2 %0, %1, %2, %0;" : "+l"(d) : "l"(a), "l"(b));
}
__device__ __forceinline__ void fadd2(unsigned long long& d, unsigned long long a) {
    asm("add.rn.f32x2 %0, %0, %1;" : "+l"(d) : "l"(a));
}
__device__ __forceinline__ unsigned long long pack2(float lo, float hi) {
    unsigned long long r;
    asm("mov.b64 %0, {%1, %2};" : "=l"(r) : "f"(lo), "f"(hi));
    return r;
}
__device__ __forceinline__ void unpack2(unsigned long long p, float& lo, float& hi) {
    asm("mov.b64 {%0, %1}, %2;" : "=f"(lo), "=f"(hi) : "l"(p));
}

// ---------------------------------------------------------------------------
// K0: one-time weight prep for all layers (folded + transposed, coalesced)
// ---------------------------------------------------------------------------
__global__ __launch_bounds__(256) void k_wprep(
    const float* __restrict__ W,   const float* __restrict__ bcv,
    const float* __restrict__ g,   const float* __restrict__ bt,
    const float* __restrict__ rm,  const float* __restrict__ rv,
    const float* __restrict__ W1,  const float* __restrict__ b1,
    const float* __restrict__ g1,  const float* __restrict__ bt1,
    const float* __restrict__ rm1, const float* __restrict__ rv1,
    const float* __restrict__ W2,  const float* __restrict__ b2,
    const float* __restrict__ g2,  const float* __restrict__ bt2,
    const float* __restrict__ rm2, const float* __restrict__ rv2)
{
    int gid = blockIdx.x * 256 + threadIdx.x;

    if (gid < CIN * MLPC) {
        int o = gid & 63, c = gid >> 6;
        float s = g[o] / sqrtf(rv[o] + EPSF);
        Wt_g[gid] = s * W[o * CIN + c];
    }
    if (gid < P2C * P1C) {
        int o = gid & 127, c = gid >> 7;
        float s1 = g1[o] / sqrtf(rv1[o] + EPSF);
        W1t_g[gid] = s1 * W1[o * P2C + c];
    }
    if (gid < P1C * P2C) {
        int o2 = gid & 63, o1 = gid >> 6;
        float s2 = g2[o2] / sqrtf(rv2[o2] + EPSF);
        W2t_g[gid] = s2 * W2[o2 * P1C + o1];
    }
    if (gid < P1C) {
        float s1 = g1[gid] / sqrtf(rv1[gid] + EPSF);
        t1_g[gid] = fmaf(s1, b1[gid] - rm1[gid], bt1[gid]);
    }
    if (gid < P2C) {
        float s2 = g2[gid] / sqrtf(rv2[gid] + EPSF);
        t2_g[gid] = fmaf(s2, b2[gid] - rm2[gid], bt2[gid]);
    }
    if (gid < MLPC) {
        int o = gid;
        float s = g[o] / sqrtf(rv[o] + EPSF);
        bs_g[o] = s * bcv[o];
        sC4_g[o] = make_float4(s * W[o * CIN + 64],
                               s * W[o * CIN + 65],
                               s * W[o * CIN + 66],
                               bt[o] - s * rm[o]);
    }
}

// ---------------------------------------------------------------------------
// K1: Th = X @ Wt, register-tiled GEMM, fp16 output.
// Block = 128 thr, 64 points; thread = 4 pts x 8 o (o paired, w as ull2).
// ---------------------------------------------------------------------------
__global__ __launch_bounds__(128) void k_pre(
    const float* __restrict__ xyz, const float* __restrict__ pts)
{
    __shared__ float Wsh[CIN * MLPC];   // [c][o]  16.75 KB
    __shared__ float Xs[CIN * 64];      // [c][m]  16.75 KB

    int tid = threadIdx.x;

    {
        const float4* src = (const float4*)Wt_g;
        float4* dst = (float4*)Wsh;
        for (int i = tid; i < CIN * MLPC / 4; i += 128) dst[i] = src[i];
    }

    int b  = blockIdx.x >> 6;              // 64 blocks per batch
    int m0 = (blockIdx.x & 63) << 6;       // 64 pts per block

    for (int i = tid; i < CIN * 16; i += 128) {
        int c = i >> 4, j = (i & 15) << 2;
        const float* src = (c < DD) ? &pts[((b << 6) + c) * NN + m0 + j]
                                    : &xyz[(b * 3 + (c - DD)) * NN + m0 + j];
        *(float4*)&Xs[c * 64 + j] = *(const float4*)src;
    }
    __syncthreads();

    if (tid < 64) {
        float x = Xs[64 * 64 + tid], y = Xs[65 * 64 + tid], z = Xs[66 * 64 + tid];
        P4_g[b * NN + m0 + tid] = make_float4(x, y, z, fmaf(z, z, fmaf(y, y, x * x)));
    }

    int om = tid & 7;        // o-base = om*8
    int pm = tid >> 3;       // pt-base = pm*4

    unsigned long long acc[4][4];   // [pt][o-pair]
#pragma unroll
    for (int p = 0; p < 4; p++)
#pragma unroll
        for (int q = 0; q < 4; q++) acc[p][q] = 0ull;

    const float* wp = &Wsh[om * 8];
    const float* xp = &Xs[pm * 4];

#pragma unroll 2
    for (int c = 0; c < CIN; c++) {
        ulonglong2 wa = *(const ulonglong2*)(wp + c * MLPC);       // o pairs 0..3
        ulonglong2 wb = *(const ulonglong2*)(wp + c * MLPC + 4);   // o pairs 4..7
        float4 xv = *(const float4*)(xp + c * 64);
        unsigned long long wv[4] = { wa.x, wa.y, wb.x, wb.y };
        float xs[4] = { xv.x, xv.y, xv.z, xv.w };
#pragma unroll
        for (int p = 0; p < 4; p++) {
            unsigned long long xx = pack2(xs[p], xs[p]);
#pragma unroll
            for (int q = 0; q < 4; q++) ffma2(acc[p][q], wv[q], xx);
        }
    }

    float4 bsA = __ldg((const float4*)&bs_g[om * 8]);
    float4 bsB = __ldg((const float4*)&bs_g[om * 8 + 4]);
    float bsv[8] = { bsA.x, bsA.y, bsA.z, bsA.w, bsB.x, bsB.y, bsB.z, bsB.w };

#pragma unroll
    for (int p = 0; p < 4; p++) {
        int gm = b * NN + m0 + pm * 4 + p;
        union { __half2 h2[4]; uint4 u4; } cvt;
#pragma unroll
        for (int q = 0; q < 4; q++) {
            float lo, hi;
            unpack2(acc[p][q], lo, hi);
            cvt.h2[q] = __floats2half2_rn(lo + bsv[2 * q], hi + bsv[2 * q + 1]);
        }
        *((uint4*)Th_g + (size_t)gm * 8 + om) = cvt.u4;
    }
}

// ---------------------------------------------------------------------------
// K2: warp-autonomous ball query + fp16 gather-max (unchanged, R8-proven)
// ---------------------------------------------------------------------------
__global__ __launch_bounds__(256) void k_ball()
{
    __shared__ int gi_sh[8][KK];

    int tid  = threadIdx.x;
    int w    = tid >> 5;
    int lane = tid & 31;
    unsigned below = (1u << lane) - 1u;

    int b  = blockIdx.x >> 9;
    int n  = ((blockIdx.x & 511) << 3) + w;
    int bN = b * NN;

    float4 q = P4_g[bN + n];

    int cnt = 0;
#pragma unroll 1
    for (int base = 0; base < NN; base += 64) {
        float4 c0 = __ldg(&P4_g[bN + base + lane]);
        float4 c1 = __ldg(&P4_g[bN + base + 32 + lane]);

        float d0 = q.w + c0.w - 2.0f * fmaf(q.z, c0.z, fmaf(q.y, c0.y, q.x * c0.x));
        float d1 = q.w + c1.w - 2.0f * fmaf(q.z, c1.z, fmaf(q.y, c1.y, q.x * c1.x));

        unsigned m0 = __ballot_sync(0xffffffffu, d0 <= R2);
        unsigned m1 = __ballot_sync(0xffffffffu, d1 <= R2);

        if (d0 <= R2) {
            int pos = cnt + __popc(m0 & below);
            if (pos < KK) gi_sh[w][pos] = base + lane;
        }
        int n0 = __popc(m0);
        if (d1 <= R2) {
            int pos = cnt + n0 + __popc(m1 & below);
            if (pos < KK) gi_sh[w][pos] = base + 32 + lane;
        }
        cnt += n0 + __popc(m1);
        if (cnt >= KK) break;
    }
    __syncwarp();

    int cap   = (cnt < KK) ? cnt : KK;
    int gidx0 = gi_sh[w][0];

    __half2 mx = __float2half2_rn(-65504.0f);
#pragma unroll
    for (int j = 0; j < KK; j++) {
        int gj = (j < cap) ? gi_sh[w][j] : gidx0;
        const __half2* tr = ((const __half2*)Th_g) + (((size_t)(bN + gj)) << 5) + lane;
        mx = __hmax2(mx, __ldg(tr));
    }
    float2 m = __half22float2(mx);

    float4 a0 = sC4_g[2 * lane];
    float4 a1 = sC4_g[2 * lane + 1];
    float u0 = a0.w - fmaf(a0.z, q.z, fmaf(a0.y, q.y, a0.x * q.x));
    float u1 = a1.w - fmaf(a1.z, q.z, fmaf(a1.y, q.y, a1.x * q.x));

    float2 outv = make_float2(fmaxf(m.x + u0, 0.0f), fmaxf(m.y + u1, 0.0f));
    *(float2*)&np_g[((size_t)(bN + n)) * MLPC + 2 * lane] = outv;
}

// ---------------------------------------------------------------------------
// K3: resnet 64->128->64 + residual ReLU, two-phase tiled GEMM.
// Block = 256 thr, 128 points. Points PAIRED (activations load as f32x2 pairs,
// no packs); weights broadcast (packed). smem regions:
//   [0,8192)       W1T [k][o]   (32KB)   --+ overlapped later by
//   [8192,16640)   Vt  [k][pt]  (33KB)   --+ X1 [o1][pt] (64KB at [0,16384))
//   [16640,24832)  W2T [k][o2]  (32KB)
// ---------------------------------------------------------------------------
__global__ __launch_bounds__(256) void k_resnet(
    const float* __restrict__ pts, float* __restrict__ out)
{
    extern __shared__ float sm[];
    float* W1sh = sm;            // 8192
    float* Vt   = sm + 8192;     // 64 x 132 = 8448
    float* W2sh = sm + 16640;    // 8192
    float* X1   = sm;            // 128 x 128 = 16384 (reuses W1sh+Vt)

    int tid = threadIdx.x;
    int m0  = blockIdx.x << 7;          // 128 points per block
    int b   = m0 >> 12;
    int n0  = m0 & (NN - 1);

    for (int i = tid; i < 2048; i += 256)
        ((float4*)W1sh)[i] = ((const float4*)W1t_g)[i];
    for (int i = tid; i < 2048; i += 256)
        ((float4*)W2sh)[i] = ((const float4*)W2t_g)[i];
    for (int i = tid; i < 2048; i += 256) {
        int pt = i >> 4, c4 = (i & 15) << 2;
        float4 v = *(const float4*)&np_g[(size_t)(m0 + pt) * MLPC + c4];
        Vt[(c4 + 0) * 132 + pt] = v.x;
        Vt[(c4 + 1) * 132 + pt] = v.y;
        Vt[(c4 + 2) * 132 + pt] = v.z;
        Vt[(c4 + 3) * 132 + pt] = v.w;
    }
    __syncthreads();

    int og = tid >> 4;      // 16 groups: o-base = og*8
    int pm = tid & 15;      // pt-base = pm*8 (4 pairs)

    // ---- Phase 1: H[o][pt] = sum_k W1T[k][o] * Vt[k][pt] ----
    unsigned long long acc1[8][4];      // [o][pt-pair]
#pragma unroll
    for (int o = 0; o < 8; o++)
#pragma unroll
        for (int p = 0; p < 4; p++) acc1[o][p] = 0ull;

    {
        const float* wrow = W1sh + og * 8;
        const float* vrow = Vt + pm * 8;
#pragma unroll 2
        for (int k = 0; k < P2C; k++) {
            float4 wa = *(const float4*)(wrow + k * P1C);
            float4 wb = *(const float4*)(wrow + k * P1C + 4);
            ulonglong2 va = *(const ulonglong2*)(vrow + k * 132);
            ulonglong2 vb = *(const ulonglong2*)(vrow + k * 132 + 4);
            unsigned long long vp[4] = { va.x, va.y, vb.x, vb.y };
            float ws[8] = { wa.x, wa.y, wa.z, wa.w, wb.x, wb.y, wb.z, wb.w };
#pragma unroll
            for (int o = 0; o < 8; o++) {
                unsigned long long ww = pack2(ws[o], ws[o]);
#pragma unroll
                for (int p = 0; p < 4; p++) ffma2(acc1[o][p], ww, vp[p]);
            }
        }
    }
    __syncthreads();   // phase-1 reads of W1sh/Vt complete before X1 overwrite

    // X1 epilogue: X1[o][pt] = relu(h + t1), stored as pairs (STS.64)
#pragma unroll
    for (int o = 0; o < 8; o++) {
        int oo = og * 8 + o;
        float t1v = __ldg(&t1_g[oo]);
#pragma unroll
        for (int p = 0; p < 4; p++) {
            float lo, hi;
            unpack2(acc1[o][p], lo, hi);
            lo = fmaxf(lo + t1v, 0.0f);
            hi = fmaxf(hi + t1v, 0.0f);
            *(unsigned long long*)&X1[oo * P1C + pm * 8 + 2 * p] = pack2(lo, hi);
        }
    }
    __syncthreads();

    // ---- Phase 2: out[o2][pt] = relu(sum_k W2T[k][o2]*X1[k][pt] + t2 + pts) ----
    int og2 = tid >> 4;     // o2-base = og2*4

    unsigned long long acc2[4][4];      // [o2][pt-pair]
#pragma unroll
    for (int o = 0; o < 4; o++)
#pragma unroll
        for (int p = 0; p < 4; p++) acc2[o][p] = 0ull;

    {
        const float* wrow = W2sh + og2 * 4;
        const float* xrow = X1 + pm * 8;
#pragma unroll 2
        for (int k = 0; k < P1C; k++) {
            float4 w = *(const float4*)(wrow + k * P2C);
            ulonglong2 xa = *(const ulonglong2*)(xrow + k * P1C);
            ulonglong2 xb = *(const ulonglong2*)(xrow + k * P1C + 4);
            unsigned long long xp[4] = { xa.x, xa.y, xb.x, xb.y };
            float ws[4] = { w.x, w.y, w.z, w.w };
#pragma unroll
            for (int o = 0; o < 4; o++) {
                unsigned long long ww = pack2(ws[o], ws[o]);
#pragma unroll
                for (int p = 0; p < 4; p++) ffma2(acc2[o][p], ww, xp[p]);
            }
        }
    }

#pragma unroll
    for (int o = 0; o < 4; o++) {
        int o2 = og2 * 4 + o;
        float t2v = __ldg(&t2_g[o2]);
        size_t goff = ((size_t)(b * P2C + o2)) * NN + n0 + pm * 8;
#pragma unroll
        for (int p = 0; p < 4; p++) {
            float2 pv = *(const float2*)&pts[goff + 2 * p];
            float lo, hi;
            unpack2(acc2[o][p], lo, hi);
            lo = fmaxf(lo + t2v + pv.x, 0.0f);
            hi = fmaxf(hi + t2v + pv.y, 0.0f);
            *(float2*)&out[goff + 2 * p] = make_float2(lo, hi);
        }
    }
}

// ---------------------------------------------------------------------------
// Launch
// ---------------------------------------------------------------------------
extern "C" void kernel_launch(void* const* d_in, const int* in_sizes, int n_in,
                              void* d_out, int out_size)
{
    (void)n_in; (void)out_size;

    const float* xyz = (const float*)d_in[0];
    const float* pts = (const float*)d_in[1];
    const float* W   = (const float*)d_in[2];
    const float* bcv = (const float*)d_in[3];
    const float* g   = (const float*)d_in[4];
    const float* bt  = (const float*)d_in[5];
    const float* rm  = (const float*)d_in[6];
    const float* rv  = (const float*)d_in[7];
    const float* W1  = (const float*)d_in[8];
    const float* b1  = (const float*)d_in[9];
    const float* g1  = (const float*)d_in[10];
    const float* bt1 = (const float*)d_in[11];
    const float* rm1 = (const float*)d_in[12];
    const float* rv1 = (const float*)d_in[13];
    const float* W2  = (const float*)d_in[14];
    const float* b2  = (const float*)d_in[15];
    const float* g2  = (const float*)d_in[16];
    const float* bt2 = (const float*)d_in[17];
    const float* rm2 = (const float*)d_in[18];
    const float* rv2 = (const float*)d_in[19];

    float* out = (float*)d_out;

    static const size_t smem3 = 24832 * sizeof(float);   // 99328 B
    cudaFuncSetAttribute(k_resnet, cudaFuncAttributeMaxDynamicSharedMemorySize,
                         (int)smem3);

    cudaMemcpyAsync(out, xyz, (size_t)in_sizes[0] * sizeof(float),
                    cudaMemcpyDeviceToDevice, 0);

    k_wprep<<<32, 256>>>(W, bcv, g, bt, rm, rv,
                         W1, b1, g1, bt1, rm1, rv1,
                         W2, b2, g2, bt2, rm2, rv2);
    k_pre<<<(BB * NN) / 64, 128>>>(xyz, pts);
    k_ball<<<(BB * NN) / 8, 256>>>();
    k_resnet<<<(BB * NN) / 128, 256, smem3>>>(pts, out + in_sizes[0]);
}